// round 1
// baseline (speedup 1.0000x reference)
#include <cuda_runtime.h>
#include <math.h>

// Problem constants
#define BB 4
#define SS 2048
#define EE 512
#define HH 8
#define DD 64
// H*D == 512 == E

// -------------------- scratch (allocation-free: __device__ globals) --------------------
__device__ __align__(16) float g_q[BB * HH * SS * DD];     // [B,H,S,D]
__device__ __align__(16) float g_k[BB * HH * SS * DD];     // [B,H,S,D]
__device__ __align__(16) float g_v[BB * HH * SS * DD];     // [B,H,S,D]
__device__ __align__(16) float g_attn[BB * SS * HH * DD];  // [B,S,H*D]

// ============================================================================
// SGEMM core: C[M=8192, N=512] = A[8192,512] @ W[512,512] + bias
// BM=128, BN=128, BK=8, 256 threads, 8x8 per-thread tile.
// mode 0: scatter to [B,H,S,D] layout (QKV). mode 1: row-major (output proj).
// ============================================================================
__device__ __forceinline__ void gemm_body(
    const float* __restrict__ A, const float* __restrict__ W,
    const float* __restrict__ bias, float* __restrict__ out, int mode)
{
    __shared__ float As[8][128];   // A transposed: As[k][m]
    __shared__ float Bs[8][128];   // Bs[k][n]

    const int tid  = threadIdx.x;
    const int row0 = blockIdx.y * 128;
    const int col0 = blockIdx.x * 128;

    const int aRow = tid >> 1;          // 0..127
    const int aCol = (tid & 1) * 4;     // 0 or 4
    const int bRow = tid >> 5;          // 0..7
    const int bCol = (tid & 31) * 4;    // 0..124

    const int tx = tid & 15;            // 0..15 -> 8 cols each
    const int ty = tid >> 4;            // 0..15 -> 8 rows each

    float acc[8][8];
#pragma unroll
    for (int i = 0; i < 8; i++)
#pragma unroll
        for (int j = 0; j < 8; j++) acc[i][j] = 0.f;

    const float* Aptr = A + (size_t)(row0 + aRow) * 512 + aCol;
    const float* Wptr = W + (size_t)bRow * 512 + col0 + bCol;

    for (int k0 = 0; k0 < 512; k0 += 8) {
        float4 av = *(const float4*)(Aptr + k0);
        float4 wv = *(const float4*)(Wptr + (size_t)k0 * 512);

        As[aCol + 0][aRow] = av.x;
        As[aCol + 1][aRow] = av.y;
        As[aCol + 2][aRow] = av.z;
        As[aCol + 3][aRow] = av.w;
        *(float4*)&Bs[bRow][bCol] = wv;
        __syncthreads();

#pragma unroll
        for (int k = 0; k < 8; k++) {
            float ar[8], br[8];
            *(float4*)(ar + 0) = *(const float4*)&As[k][ty * 8 + 0];
            *(float4*)(ar + 4) = *(const float4*)&As[k][ty * 8 + 4];
            *(float4*)(br + 0) = *(const float4*)&Bs[k][tx * 8 + 0];
            *(float4*)(br + 4) = *(const float4*)&Bs[k][tx * 8 + 4];
#pragma unroll
            for (int i = 0; i < 8; i++)
#pragma unroll
                for (int j = 0; j < 8; j++)
                    acc[i][j] += ar[i] * br[j];
        }
        __syncthreads();
    }

    // epilogue
#pragma unroll
    for (int i = 0; i < 8; i++) {
        const int r    = row0 + ty * 8 + i;
        const int colb = col0 + tx * 8;       // multiple of 8; never crosses a 64-wide head
        if (mode == 0) {
            const int bb = r >> 11;           // r / 2048
            const int s  = r & 2047;
            const int h  = colb >> 6;
            const int d0 = colb & 63;
            float* o = out + ((size_t)((bb * HH + h) * SS + s)) * DD + d0;
#pragma unroll
            for (int j = 0; j < 8; j++) o[j] = acc[i][j] + bias[colb + j];
        } else {
            float* o = out + (size_t)r * 512 + colb;
#pragma unroll
            for (int j = 0; j < 8; j++) o[j] = acc[i][j] + bias[colb + j];
        }
    }
}

__global__ __launch_bounds__(256, 2) void qkv_kernel(
    const float* __restrict__ iq, const float* __restrict__ ik, const float* __restrict__ iv,
    const float* __restrict__ wq, const float* __restrict__ bq,
    const float* __restrict__ wk, const float* __restrict__ bk,
    const float* __restrict__ wv, const float* __restrict__ bv)
{
    const float *A, *W, *bi;
    float* out;
    if (blockIdx.z == 0)      { A = iq; W = wq; bi = bq; out = g_q; }
    else if (blockIdx.z == 1) { A = ik; W = wk; bi = bk; out = g_k; }
    else                      { A = iv; W = wv; bi = bv; out = g_v; }
    gemm_body(A, W, bi, out, 0);
}

__global__ __launch_bounds__(256, 2) void oproj_kernel(
    const float* __restrict__ wo, const float* __restrict__ bo, float* __restrict__ out)
{
    gemm_body(g_attn, wo, bo, out, 1);
}

// ============================================================================
// Flash attention, fp32. Block = (h, q-tile of 64, b). 256 threads.
// Thread (ty,tx): ty=tid/16 owns q-rows 4ty..4ty+3; tx=tid%16 owns a 4-wide
// slice of k-cols (scores) / d-cols (output).
// Q,K kept d-major (transposed) in smem -> conflict-free LDS.128.
// Matches reference: score -> mask(-1e9) -> *1/sqrt(D) -> softmax.
// ============================================================================
#define PAD 68                      // 64 + 4, keeps float4 alignment (68*4B % 16 == 0)
#define ATTN_SMEM (4 * 64 * PAD * 4)

__global__ __launch_bounds__(256, 2) void attn_kernel(const int* __restrict__ mask)
{
    extern __shared__ float sm[];
    float* QsT = sm;                 // [d=64][row pad 68]
    float* KsT = sm + 64 * PAD;      // [d=64][kcol pad 68]
    float* Vs  = sm + 2 * 64 * PAD;  // [kv=64][d pad 68]
    float* Ps  = sm + 3 * 64 * PAD;  // [qrow=64][kcol pad 68]

    const int tid = threadIdx.x;
    const int tx  = tid & 15;
    const int ty  = tid >> 4;
    const int h   = blockIdx.x;
    const int q0  = blockIdx.y * 64;
    const int b   = blockIdx.z;

    const size_t qkv_base = ((size_t)(b * HH + h)) * SS * DD;

    // ---- load Q tile transposed ----
    {
        const float* gq = g_q + qkv_base + (size_t)q0 * DD;
#pragma unroll
        for (int i = 0; i < 4; i++) {
            const int r = ty + i * 16;
            const int d = tx * 4;
            float4 v = *(const float4*)(gq + r * 64 + d);
            QsT[(d + 0) * PAD + r] = v.x;
            QsT[(d + 1) * PAD + r] = v.y;
            QsT[(d + 2) * PAD + r] = v.z;
            QsT[(d + 3) * PAD + r] = v.w;
        }
    }

    float acc[4][4];
#pragma unroll
    for (int i = 0; i < 4; i++)
#pragma unroll
        for (int j = 0; j < 4; j++) acc[i][j] = 0.f;

    float mrow[4], lrow[4];
#pragma unroll
    for (int i = 0; i < 4; i++) { mrow[i] = __int_as_float(0xff800000); lrow[i] = 0.f; }

    const int* mbase0 = mask + ((size_t)b * SS + q0) * SS;

    for (int k0 = 0; k0 < SS; k0 += 64) {
        __syncthreads();  // previous iteration's PV reads done before overwrite

        // ---- load K (transposed) and V tiles ----
        const float* gk = g_k + qkv_base + (size_t)k0 * DD;
        const float* gv = g_v + qkv_base + (size_t)k0 * DD;
#pragma unroll
        for (int i = 0; i < 4; i++) {
            const int r = ty + i * 16;
            const int d = tx * 4;
            float4 kv = *(const float4*)(gk + r * 64 + d);
            KsT[(d + 0) * PAD + r] = kv.x;
            KsT[(d + 1) * PAD + r] = kv.y;
            KsT[(d + 2) * PAD + r] = kv.z;
            KsT[(d + 3) * PAD + r] = kv.w;
            float4 vv = *(const float4*)(gv + r * 64 + d);
            *(float4*)&Vs[r * PAD + d] = vv;
        }
        __syncthreads();

        // ---- scores: sv[i][j] = sum_d Q[4ty+i][d] * K[4tx+j][d] ----
        float sv[4][4];
#pragma unroll
        for (int i = 0; i < 4; i++)
#pragma unroll
            for (int j = 0; j < 4; j++) sv[i][j] = 0.f;

#pragma unroll 8
        for (int d = 0; d < 64; d++) {
            float qa[4], ka[4];
            *(float4*)qa = *(const float4*)&QsT[d * PAD + ty * 4];
            *(float4*)ka = *(const float4*)&KsT[d * PAD + tx * 4];
#pragma unroll
            for (int i = 0; i < 4; i++)
#pragma unroll
                for (int j = 0; j < 4; j++)
                    sv[i][j] += qa[i] * ka[j];
        }

        // ---- mask, scale, online softmax ----
        const int* mb = mbase0 + k0 + tx * 4;
#pragma unroll
        for (int i = 0; i < 4; i++) {
            const int r = ty * 4 + i;
            int4 mk = *(const int4*)(mb + (size_t)r * SS);
            sv[i][0] = (mk.x ? sv[i][0] : -1e9f) * 0.125f;
            sv[i][1] = (mk.y ? sv[i][1] : -1e9f) * 0.125f;
            sv[i][2] = (mk.z ? sv[i][2] : -1e9f) * 0.125f;
            sv[i][3] = (mk.w ? sv[i][3] : -1e9f) * 0.125f;

            float mx = fmaxf(fmaxf(sv[i][0], sv[i][1]), fmaxf(sv[i][2], sv[i][3]));
#pragma unroll
            for (int o = 8; o; o >>= 1) mx = fmaxf(mx, __shfl_xor_sync(0xffffffffu, mx, o));

            const float newm = fmaxf(mrow[i], mx);
            const float corr = __expf(mrow[i] - newm);
            mrow[i] = newm;

            float rs = 0.f;
#pragma unroll
            for (int j = 0; j < 4; j++) {
                float p = __expf(sv[i][j] - newm);
                sv[i][j] = p;
                rs += p;
            }
#pragma unroll
            for (int o = 8; o; o >>= 1) rs += __shfl_xor_sync(0xffffffffu, rs, o);

            lrow[i] = lrow[i] * corr + rs;
            acc[i][0] *= corr; acc[i][1] *= corr; acc[i][2] *= corr; acc[i][3] *= corr;

            *(float4*)&Ps[r * PAD + tx * 4] = make_float4(sv[i][0], sv[i][1], sv[i][2], sv[i][3]);
        }
        __syncthreads();

        // ---- PV: acc[i][j] += sum_c P[4ty+i][c] * V[c][4tx+j] ----
#pragma unroll 4
        for (int c4 = 0; c4 < 64; c4 += 4) {
            float4 vr0 = *(const float4*)&Vs[(c4 + 0) * PAD + tx * 4];
            float4 vr1 = *(const float4*)&Vs[(c4 + 1) * PAD + tx * 4];
            float4 vr2 = *(const float4*)&Vs[(c4 + 2) * PAD + tx * 4];
            float4 vr3 = *(const float4*)&Vs[(c4 + 3) * PAD + tx * 4];
#pragma unroll
            for (int i = 0; i < 4; i++) {
                float4 pv = *(const float4*)&Ps[(ty * 4 + i) * PAD + c4];
                acc[i][0] += pv.x * vr0.x + pv.y * vr1.x + pv.z * vr2.x + pv.w * vr3.x;
                acc[i][1] += pv.x * vr0.y + pv.y * vr1.y + pv.z * vr2.y + pv.w * vr3.y;
                acc[i][2] += pv.x * vr0.z + pv.y * vr1.z + pv.z * vr2.z + pv.w * vr3.z;
                acc[i][3] += pv.x * vr0.w + pv.y * vr1.w + pv.z * vr2.w + pv.w * vr3.w;
            }
        }
    }

    // ---- epilogue: O /= l, write [B,S,H*D] ----
#pragma unroll
    for (int i = 0; i < 4; i++) {
        const int r = ty * 4 + i;
        const float inv = 1.0f / lrow[i];
        float4 o = make_float4(acc[i][0] * inv, acc[i][1] * inv, acc[i][2] * inv, acc[i][3] * inv);
        *(float4*)(g_attn + ((size_t)(b * SS + q0 + r)) * 512 + h * 64 + tx * 4) = o;
    }
}

// ============================================================================
extern "C" void kernel_launch(void* const* d_in, const int* in_sizes, int n_in,
                              void* d_out, int out_size)
{
    const float* iq   = (const float*)d_in[0];
    const float* ik   = (const float*)d_in[1];
    const float* iv   = (const float*)d_in[2];
    const int*   mask = (const int*)  d_in[3];
    const float* wq   = (const float*)d_in[4];
    const float* bq   = (const float*)d_in[5];
    const float* wk   = (const float*)d_in[6];
    const float* bk   = (const float*)d_in[7];
    const float* wv   = (const float*)d_in[8];
    const float* bv   = (const float*)d_in[9];
    const float* wo   = (const float*)d_in[10];
    const float* bo   = (const float*)d_in[11];
    float* out = (float*)d_out;

    // QKV projections: 3 GEMMs of [8192,512]x[512,512]
    dim3 gq(512 / 128, (BB * SS) / 128, 3);
    qkv_kernel<<<gq, 256>>>(iq, ik, iv, wq, bq, wk, bk, wv, bv);

    // Flash attention
    cudaFuncSetAttribute(attn_kernel, cudaFuncAttributeMaxDynamicSharedMemorySize, ATTN_SMEM);
    dim3 ga(HH, SS / 64, BB);
    attn_kernel<<<ga, 256, ATTN_SMEM>>>(mask);

    // Output projection
    dim3 go(512 / 128, (BB * SS) / 128);
    oproj_kernel<<<go, 256>>>(wo, bo, out);
}

// round 3
// speedup vs baseline: 1.7610x; 1.7610x over previous
#include <cuda_runtime.h>
#include <cuda_bf16.h>
#include <stdint.h>

// ---------------- problem constants ----------------
#define BB 4
#define SS 2048
#define HH 8
#define DD 64
#define MKELEM (8192*512)
#define KNELEM (512*512)
#define BHSD (BB*HH*SS*DD)

// ---------------- scratch (__device__ globals, allocation-free) ----------------
__device__ __align__(16) __nv_bfloat16 g_act_hi[3*MKELEM];
__device__ __align__(16) __nv_bfloat16 g_act_lo[3*MKELEM];
__device__ __align__(16) __nv_bfloat16 g_wt_hi[4*KNELEM];   // transposed [n][k]
__device__ __align__(16) __nv_bfloat16 g_wt_lo[4*KNELEM];
__device__ __align__(16) __nv_bfloat16 g_qh[BHSD], g_ql[BHSD];   // [b,h,s,d]
__device__ __align__(16) __nv_bfloat16 g_kh[BHSD], g_kl[BHSD];
__device__ __align__(16) __nv_bfloat16 g_vh[BHSD], g_vl[BHSD];
__device__ __align__(16) __nv_bfloat16 g_oh[MKELEM], g_ol[MKELEM];  // [row][512]
__device__ uint32_t g_mbits[BB*64*SS];                      // [b][kchunk][q]

// ---------------- helpers ----------------
__device__ __forceinline__ void mma16816(float* d,
    uint32_t a0, uint32_t a1, uint32_t a2, uint32_t a3, uint32_t b0, uint32_t b1)
{
    asm volatile(
        "mma.sync.aligned.m16n8k16.row.col.f32.bf16.bf16.f32 "
        "{%0,%1,%2,%3},{%4,%5,%6,%7},{%8,%9},{%0,%1,%2,%3};"
        : "+f"(d[0]), "+f"(d[1]), "+f"(d[2]), "+f"(d[3])
        : "r"(a0), "r"(a1), "r"(a2), "r"(a3), "r"(b0), "r"(b1));
}

__device__ __forceinline__ uint32_t packbf(float x0, float x1) {
    __nv_bfloat162 t = __floats2bfloat162_rn(x0, x1);   // x0 -> low half
    return reinterpret_cast<uint32_t&>(t);
}
__device__ __forceinline__ uint32_t packres(float x0, float x1, uint32_t h) {
    float f0 = __uint_as_float(h << 16);
    float f1 = __uint_as_float(h & 0xffff0000u);
    return packbf(x0 - f0, x1 - f1);
}
__device__ __forceinline__ void split1(float x, __nv_bfloat16& h, __nv_bfloat16& l) {
    h = __float2bfloat16(x);
    l = __float2bfloat16(x - __bfloat162float(h));
}

// ============================================================================
// activation split: fp32 -> bf16 hi/lo, z in {q,k,v}
// ============================================================================
__global__ void split_act_kernel(const float* __restrict__ s0, const float* __restrict__ s1,
                                 const float* __restrict__ s2) {
    const int z = blockIdx.z;
    const float* src = (z == 0) ? s0 : (z == 1) ? s1 : s2;
    __nv_bfloat16* hi = g_act_hi + (size_t)z * MKELEM;
    __nv_bfloat16* lo = g_act_lo + (size_t)z * MKELEM;
    size_t idx = (size_t)blockIdx.x * blockDim.x + threadIdx.x;
    float4 v = ((const float4*)src)[idx];
    __nv_bfloat16 h0, h1, h2, h3, l0, l1, l2, l3;
    split1(v.x, h0, l0); split1(v.y, h1, l1); split1(v.z, h2, l2); split1(v.w, h3, l3);
    ((__nv_bfloat162*)hi)[idx*2+0] = __halves2bfloat162(h0, h1);
    ((__nv_bfloat162*)hi)[idx*2+1] = __halves2bfloat162(h2, h3);
    ((__nv_bfloat162*)lo)[idx*2+0] = __halves2bfloat162(l0, l1);
    ((__nv_bfloat162*)lo)[idx*2+1] = __halves2bfloat162(l2, l3);
}

// ============================================================================
// weight transpose + split: W[k][n] -> [n][k] hi/lo
// ============================================================================
__global__ void wsplit_kernel(const float* __restrict__ wq, const float* __restrict__ wk,
                              const float* __restrict__ wv, const float* __restrict__ wo) {
    __shared__ float t[32][33];
    const int z = blockIdx.z;
    const float* W = (z == 0) ? wq : (z == 1) ? wk : (z == 2) ? wv : wo;
    const int n0 = blockIdx.x * 32, k0 = blockIdx.y * 32;
    const int tx = threadIdx.x, ty = threadIdx.y;
#pragma unroll
    for (int i = 0; i < 32; i += 8) t[ty+i][tx] = W[(size_t)(k0+ty+i)*512 + n0 + tx];
    __syncthreads();
    __nv_bfloat16* Hi = g_wt_hi + (size_t)z * KNELEM;
    __nv_bfloat16* Lo = g_wt_lo + (size_t)z * KNELEM;
#pragma unroll
    for (int i = 0; i < 32; i += 8) {
        float x = t[tx][ty+i];
        __nv_bfloat16 h, l; split1(x, h, l);
        Hi[(size_t)(n0+ty+i)*512 + k0 + tx] = h;
        Lo[(size_t)(n0+ty+i)*512 + k0 + tx] = l;
    }
}

// ============================================================================
// mask -> bit pack: g_mbits[(b*64+kc)*2048 + q], bit i of word = mask[b][q][kc*32+i]
// ============================================================================
__global__ void maskpack_kernel(const int* __restrict__ mask) {
    int wid = blockIdx.x * 8 + (threadIdx.x >> 5);
    int lane = threadIdx.x & 31;
    int kc = wid & 63;
    int q  = (wid >> 6) & 2047;
    int b  = wid >> 17;
    int v = mask[((size_t)b*SS + q)*SS + kc*32 + lane];
    uint32_t bits = __ballot_sync(0xffffffffu, v != 0);
    if (lane == 0) g_mbits[((size_t)b*64 + kc)*SS + q] = bits;
}

// ============================================================================
// mma.sync GEMM: C[8192,512] = A @ W + bias, bf16x3 compensated.
// Block 128x128, 8 warps (4m x 2n), warp tile 32x64. K-chunks of 32.
// phase 0 (z=0..2): out -> g_{q,k,v}{h,l} bf16 hi/lo [b,h,s,d]
// phase 1: A = g_o{h,l}, W = wt[3], out -> fp32 outp row-major
// ============================================================================
__global__ __launch_bounds__(256) void gemm_mma_kernel(
    int phase, const float* __restrict__ bq, const float* __restrict__ bk,
    const float* __restrict__ bv, float* __restrict__ outp)
{
    __shared__ __nv_bfloat16 sAh[128*40], sAl[128*40], sBh[128*40], sBl[128*40];

    const int tid = threadIdx.x;
    const int w = tid >> 5, lane = tid & 31;
    const int g = lane >> 2, t2 = (lane & 3) * 2;
    const int z = blockIdx.z;
    const int n0 = blockIdx.x * 128, m0 = blockIdx.y * 128;
    const int wr = (w & 3) * 32, wc = (w >> 2) * 64;

    const __nv_bfloat16 *Ah, *Al, *Bh, *Bl;
    const float* bias;
    if (phase == 0) {
        Ah = g_act_hi + (size_t)z * MKELEM; Al = g_act_lo + (size_t)z * MKELEM;
        Bh = g_wt_hi + (size_t)z * KNELEM;  Bl = g_wt_lo + (size_t)z * KNELEM;
        bias = (z == 0) ? bq : (z == 1) ? bk : bv;
    } else {
        Ah = g_oh; Al = g_ol;
        Bh = g_wt_hi + (size_t)3 * KNELEM; Bl = g_wt_lo + (size_t)3 * KNELEM;
        bias = bq;
    }

    float dacc[2][8][4];
#pragma unroll
    for (int mi = 0; mi < 2; mi++)
#pragma unroll
        for (int j = 0; j < 8; j++)
#pragma unroll
            for (int c = 0; c < 4; c++) dacc[mi][j][c] = 0.f;

    for (int kc = 0; kc < 16; kc++) {
        __syncthreads();
#pragma unroll
        for (int i = 0; i < 2; i++) {
            int idx = tid + 256*i;
            int r = idx >> 2, c = (idx & 3) * 8;
            *(uint4*)(sAh + r*40 + c) = *(const uint4*)(Ah + (size_t)(m0+r)*512 + kc*32 + c);
            *(uint4*)(sAl + r*40 + c) = *(const uint4*)(Al + (size_t)(m0+r)*512 + kc*32 + c);
            *(uint4*)(sBh + r*40 + c) = *(const uint4*)(Bh + (size_t)(n0+r)*512 + kc*32 + c);
            *(uint4*)(sBl + r*40 + c) = *(const uint4*)(Bl + (size_t)(n0+r)*512 + kc*32 + c);
        }
        __syncthreads();

#pragma unroll
        for (int ks = 0; ks < 2; ks++) {
            const int kb = ks*16 + t2;
#pragma unroll
            for (int mi = 0; mi < 2; mi++) {
                const int ar = wr + mi*16;
                uint32_t ah0 = *(const uint32_t*)(sAh + (ar+g)*40 + kb);
                uint32_t ah1 = *(const uint32_t*)(sAh + (ar+g+8)*40 + kb);
                uint32_t ah2 = *(const uint32_t*)(sAh + (ar+g)*40 + kb + 8);
                uint32_t ah3 = *(const uint32_t*)(sAh + (ar+g+8)*40 + kb + 8);
                uint32_t al0 = *(const uint32_t*)(sAl + (ar+g)*40 + kb);
                uint32_t al1 = *(const uint32_t*)(sAl + (ar+g+8)*40 + kb);
                uint32_t al2 = *(const uint32_t*)(sAl + (ar+g)*40 + kb + 8);
                uint32_t al3 = *(const uint32_t*)(sAl + (ar+g+8)*40 + kb + 8);
#pragma unroll
                for (int j = 0; j < 8; j++) {
                    uint32_t bh0 = *(const uint32_t*)(sBh + (wc+8*j+g)*40 + kb);
                    uint32_t bh1 = *(const uint32_t*)(sBh + (wc+8*j+g)*40 + kb + 8);
                    uint32_t bl0 = *(const uint32_t*)(sBl + (wc+8*j+g)*40 + kb);
                    uint32_t bl1 = *(const uint32_t*)(sBl + (wc+8*j+g)*40 + kb + 8);
                    mma16816(dacc[mi][j], ah0, ah1, ah2, ah3, bh0, bh1);
                    mma16816(dacc[mi][j], ah0, ah1, ah2, ah3, bl0, bl1);
                    mma16816(dacc[mi][j], al0, al1, al2, al3, bh0, bh1);
                }
            }
        }
    }

    // epilogue
    __nv_bfloat16 *oh = nullptr, *ol = nullptr;
    if (phase == 0) {
        oh = (z == 0) ? g_qh : (z == 1) ? g_kh : g_vh;
        ol = (z == 0) ? g_ql : (z == 1) ? g_kl : g_vl;
    }
#pragma unroll
    for (int mi = 0; mi < 2; mi++) {
        const int r0 = m0 + wr + mi*16 + g;
#pragma unroll
        for (int j = 0; j < 8; j++) {
            const int col = n0 + wc + 8*j + t2;
            float2 bs = *(const float2*)(bias + col);
            float v0 = dacc[mi][j][0] + bs.x, v1 = dacc[mi][j][1] + bs.y;
            float v2 = dacc[mi][j][2] + bs.x, v3 = dacc[mi][j][3] + bs.y;
            if (phase == 1) {
                *(float2*)(outp + (size_t)r0*512 + col) = make_float2(v0, v1);
                *(float2*)(outp + (size_t)(r0+8)*512 + col) = make_float2(v2, v3);
            } else {
                const int bidx = r0 >> 11, s = r0 & 2047;
                const int hh = col >> 6, d = col & 63;
                size_t o0 = ((size_t)(bidx*HH + hh)*SS + s)*64 + d;
                size_t o8 = o0 + 8*64;
                uint32_t h0 = packbf(v0, v1);
                *(uint32_t*)(oh + o0) = h0;
                *(uint32_t*)(ol + o0) = packres(v0, v1, h0);
                uint32_t h8 = packbf(v2, v3);
                *(uint32_t*)(oh + o8) = h8;
                *(uint32_t*)(ol + o8) = packres(v2, v3, h8);
            }
        }
    }
}

// ============================================================================
// Flash attention via mma.sync bf16x3. Block=(h, 128 q-rows, b), 8 warps.
// Warp owns 16 q-rows. K staged [s][d] (pad 72), V transposed [d][s] (pad 66).
// Matches reference: score -> mask(-1e9) -> *0.125 -> online softmax.
// ============================================================================
__global__ __launch_bounds__(256) void attn_kernel()
{
    __shared__ __nv_bfloat16 sKh[64*72], sKl[64*72];
    __shared__ __nv_bfloat16 sVh[64*66], sVl[64*66];
    __shared__ uint32_t sMask[128*2];

    const int tid = threadIdx.x;
    const int w = tid >> 5, lane = tid & 31;
    const int g = lane >> 2, t2 = (lane & 3) * 2;
    const int h = blockIdx.x, q0 = blockIdx.y * 128, b = blockIdx.z;
    const int mr = w * 16;
    const size_t bh = (size_t)(b*HH + h) * SS;

    // Q fragments, register-resident for the whole k-loop
    uint32_t qhf[4][4], qlf[4][4];
    {
        const __nv_bfloat16* qh = g_qh + (bh + q0 + mr) * DD;
        const __nv_bfloat16* ql = g_ql + (bh + q0 + mr) * DD;
#pragma unroll
        for (int kk = 0; kk < 4; kk++) {
            const int kb = kk*16 + t2;
            qhf[kk][0] = *(const uint32_t*)(qh + g*64 + kb);
            qhf[kk][1] = *(const uint32_t*)(qh + (g+8)*64 + kb);
            qhf[kk][2] = *(const uint32_t*)(qh + g*64 + kb + 8);
            qhf[kk][3] = *(const uint32_t*)(qh + (g+8)*64 + kb + 8);
            qlf[kk][0] = *(const uint32_t*)(ql + g*64 + kb);
            qlf[kk][1] = *(const uint32_t*)(ql + (g+8)*64 + kb);
            qlf[kk][2] = *(const uint32_t*)(ql + g*64 + kb + 8);
            qlf[kk][3] = *(const uint32_t*)(ql + (g+8)*64 + kb + 8);
        }
    }

    float oacc[8][4];
#pragma unroll
    for (int j = 0; j < 8; j++)
#pragma unroll
        for (int c = 0; c < 4; c++) oacc[j][c] = 0.f;
    float m0 = __int_as_float(0xff800000), m1 = m0;   // -inf
    float l0 = 0.f, l1 = 0.f;

    for (int kt = 0; kt < 32; kt++) {
        const int k0 = kt * 64;
        __syncthreads();
        // ---- stage K (natural) and V (transposed), hi+lo ----
#pragma unroll
        for (int i = 0; i < 2; i++) {
            const int idx = tid + 256*i;
            const int s = idx >> 3, c8 = (idx & 7) * 8;
            const size_t src = (bh + k0 + s) * 64 + c8;
            *(uint4*)(sKh + s*72 + c8) = *(const uint4*)(g_kh + src);
            *(uint4*)(sKl + s*72 + c8) = *(const uint4*)(g_kl + src);
            uint4 vh = *(const uint4*)(g_vh + src);
            uint4 vl = *(const uint4*)(g_vl + src);
            const __nv_bfloat16* vhe = (const __nv_bfloat16*)&vh;
            const __nv_bfloat16* vle = (const __nv_bfloat16*)&vl;
#pragma unroll
            for (int e = 0; e < 8; e++) {
                sVh[(c8+e)*66 + s] = vhe[e];
                sVl[(c8+e)*66 + s] = vle[e];
            }
        }
        {   // mask bits: 128 rows x 2 words
            const int r = tid >> 1, wsel = tid & 1;
            sMask[r*2 + wsel] = g_mbits[((size_t)b*64 + (k0>>5) + wsel)*SS + q0 + r];
        }
        __syncthreads();

        // ---- scores: S = Q K^T (3-pass) ----
        float sacc[8][4];
#pragma unroll
        for (int j = 0; j < 8; j++)
#pragma unroll
            for (int c = 0; c < 4; c++) sacc[j][c] = 0.f;
#pragma unroll
        for (int j = 0; j < 8; j++) {
#pragma unroll
            for (int kk = 0; kk < 4; kk++) {
                const int kb = kk*16 + t2;
                uint32_t bh0 = *(const uint32_t*)(sKh + (8*j+g)*72 + kb);
                uint32_t bh1 = *(const uint32_t*)(sKh + (8*j+g)*72 + kb + 8);
                uint32_t bl0 = *(const uint32_t*)(sKl + (8*j+g)*72 + kb);
                uint32_t bl1 = *(const uint32_t*)(sKl + (8*j+g)*72 + kb + 8);
                mma16816(sacc[j], qhf[kk][0], qhf[kk][1], qhf[kk][2], qhf[kk][3], bh0, bh1);
                mma16816(sacc[j], qhf[kk][0], qhf[kk][1], qhf[kk][2], qhf[kk][3], bl0, bl1);
                mma16816(sacc[j], qlf[kk][0], qlf[kk][1], qlf[kk][2], qlf[kk][3], bh0, bh1);
            }
        }

        // ---- mask + scale ----
        const uint32_t mwa0 = sMask[(mr+g)*2],     mwa1 = sMask[(mr+g)*2 + 1];
        const uint32_t mwb0 = sMask[(mr+g+8)*2],   mwb1 = sMask[(mr+g+8)*2 + 1];
#pragma unroll
        for (int j = 0; j < 8; j++) {
            const int sh = (j & 3)*8 + t2;
            const uint32_t wa = (j < 4) ? mwa0 : mwa1;
            const uint32_t wb = (j < 4) ? mwb0 : mwb1;
            sacc[j][0] = (((wa >> sh) & 1)     ? sacc[j][0] : -1e9f) * 0.125f;
            sacc[j][1] = (((wa >> (sh+1)) & 1) ? sacc[j][1] : -1e9f) * 0.125f;
            sacc[j][2] = (((wb >> sh) & 1)     ? sacc[j][2] : -1e9f) * 0.125f;
            sacc[j][3] = (((wb >> (sh+1)) & 1) ? sacc[j][3] : -1e9f) * 0.125f;
        }

        // ---- online softmax (rows g and g+8) ----
        float mx0 = sacc[0][0], mx1 = sacc[0][2];
#pragma unroll
        for (int j = 0; j < 8; j++) {
            mx0 = fmaxf(mx0, fmaxf(sacc[j][0], sacc[j][1]));
            mx1 = fmaxf(mx1, fmaxf(sacc[j][2], sacc[j][3]));
        }
#pragma unroll
        for (int o = 1; o <= 2; o <<= 1) {
            mx0 = fmaxf(mx0, __shfl_xor_sync(0xffffffffu, mx0, o));
            mx1 = fmaxf(mx1, __shfl_xor_sync(0xffffffffu, mx1, o));
        }
        const float nm0 = fmaxf(m0, mx0), nm1 = fmaxf(m1, mx1);
        const float cr0 = __expf(m0 - nm0), cr1 = __expf(m1 - nm1);
        m0 = nm0; m1 = nm1;

        float rs0 = 0.f, rs1 = 0.f;
#pragma unroll
        for (int j = 0; j < 8; j++) {
            sacc[j][0] = __expf(sacc[j][0] - nm0);
            sacc[j][1] = __expf(sacc[j][1] - nm0);
            sacc[j][2] = __expf(sacc[j][2] - nm1);
            sacc[j][3] = __expf(sacc[j][3] - nm1);
            rs0 += sacc[j][0] + sacc[j][1];
            rs1 += sacc[j][2] + sacc[j][3];
        }
#pragma unroll
        for (int o = 1; o <= 2; o <<= 1) {
            rs0 += __shfl_xor_sync(0xffffffffu, rs0, o);
            rs1 += __shfl_xor_sync(0xffffffffu, rs1, o);
        }
        l0 = l0 * cr0 + rs0;
        l1 = l1 * cr1 + rs1;
#pragma unroll
        for (int j = 0; j < 8; j++) {
            oacc[j][0] *= cr0; oacc[j][1] *= cr0;
            oacc[j][2] *= cr1; oacc[j][3] *= cr1;
        }

        // ---- PV: O += P V (3-pass, P packed from D-fragments in regs) ----
#pragma unroll
        for (int kk = 0; kk < 4; kk++) {
            const int j0 = 2*kk, j1 = 2*kk + 1;
            uint32_t ah0 = packbf(sacc[j0][0], sacc[j0][1]);
            uint32_t ah1 = packbf(sacc[j0][2], sacc[j0][3]);
            uint32_t ah2 = packbf(sacc[j1][0], sacc[j1][1]);
            uint32_t ah3 = packbf(sacc[j1][2], sacc[j1][3]);
            uint32_t al0 = packres(sacc[j0][0], sacc[j0][1], ah0);
            uint32_t al1 = packres(sacc[j0][2], sacc[j0][3], ah1);
            uint32_t al2 = packres(sacc[j1][0], sacc[j1][1], ah2);
            uint32_t al3 = packres(sacc[j1][2], sacc[j1][3], ah3);
            const int kb = kk*16 + t2;
#pragma unroll
            for (int j2 = 0; j2 < 8; j2++) {
                uint32_t vh0 = *(const uint32_t*)(sVh + (8*j2+g)*66 + kb);
                uint32_t vh1 = *(const uint32_t*)(sVh + (8*j2+g)*66 + kb + 8);
                uint32_t vl0 = *(const uint32_t*)(sVl + (8*j2+g)*66 + kb);
                uint32_t vl1 = *(const uint32_t*)(sVl + (8*j2+g)*66 + kb + 8);
                mma16816(oacc[j2], ah0, ah1, ah2, ah3, vh0, vh1);
                mma16816(oacc[j2], ah0, ah1, ah2, ah3, vl0, vl1);
                mma16816(oacc[j2], al0, al1, al2, al3, vh0, vh1);
            }
        }
    }

    // ---- epilogue: O/l -> bf16 hi/lo [row][512] ----
    const float inv0 = 1.f / l0, inv1 = 1.f / l1;
    const size_t row0 = (size_t)b*SS + q0 + mr + g;
#pragma unroll
    for (int j2 = 0; j2 < 8; j2++) {
        const int d = 8*j2 + t2;
        float v0 = oacc[j2][0] * inv0, v1 = oacc[j2][1] * inv0;
        float v2 = oacc[j2][2] * inv1, v3 = oacc[j2][3] * inv1;
        uint32_t h0 = packbf(v0, v1);
        *(uint32_t*)(g_oh + row0*512 + h*64 + d) = h0;
        *(uint32_t*)(g_ol + row0*512 + h*64 + d) = packres(v0, v1, h0);
        uint32_t h8 = packbf(v2, v3);
        *(uint32_t*)(g_oh + (row0+8)*512 + h*64 + d) = h8;
        *(uint32_t*)(g_ol + (row0+8)*512 + h*64 + d) = packres(v2, v3, h8);
    }
}

// ============================================================================
extern "C" void kernel_launch(void* const* d_in, const int* in_sizes, int n_in,
                              void* d_out, int out_size)
{
    const float* iq   = (const float*)d_in[0];
    const float* ik   = (const float*)d_in[1];
    const float* iv   = (const float*)d_in[2];
    const int*   mask = (const int*)  d_in[3];
    const float* wq   = (const float*)d_in[4];
    const float* bq   = (const float*)d_in[5];
    const float* wk   = (const float*)d_in[6];
    const float* bk   = (const float*)d_in[7];
    const float* wv   = (const float*)d_in[8];
    const float* bv   = (const float*)d_in[9];
    const float* wo   = (const float*)d_in[10];
    const float* bo   = (const float*)d_in[11];
    float* out = (float*)d_out;

    split_act_kernel<<<dim3(MKELEM/4/256, 1, 3), 256>>>(iq, ik, iv);
    wsplit_kernel<<<dim3(16, 16, 4), dim3(32, 8)>>>(wq, wk, wv, wo);
    maskpack_kernel<<<BB*SS*64/8, 256>>>(mask);
    gemm_mma_kernel<<<dim3(4, 64, 3), 256>>>(0, bq, bk, bv, nullptr);
    attn_kernel<<<dim3(HH, SS/128, BB), 256>>>();
    gemm_mma_kernel<<<dim3(4, 64, 1), 256>>>(1, bo, nullptr, nullptr, out);
}

// round 4
// speedup vs baseline: 2.2338x; 1.2685x over previous
#include <cuda_runtime.h>
#include <cuda_bf16.h>
#include <stdint.h>

// ---------------- problem constants ----------------
#define BB 4
#define SS 2048
#define HH 8
#define DD 64
#define MKELEM (8192*512)
#define KNELEM (512*512)
#define BHSD (BB*HH*SS*DD)

// ---------------- scratch (__device__ globals, allocation-free) ----------------
__device__ __align__(16) __nv_bfloat16 g_act_hi[3*MKELEM];
__device__ __align__(16) __nv_bfloat16 g_act_lo[3*MKELEM];
__device__ __align__(16) __nv_bfloat16 g_wt_hi[4*KNELEM];   // transposed [n][k]
__device__ __align__(16) __nv_bfloat16 g_wt_lo[4*KNELEM];
__device__ __align__(16) __nv_bfloat16 g_qh[BHSD], g_ql[BHSD];   // [b,h,s,d]
__device__ __align__(16) __nv_bfloat16 g_kh[BHSD], g_kl[BHSD];
__device__ __align__(16) __nv_bfloat16 g_vh[BHSD], g_vl[BHSD];
__device__ __align__(16) __nv_bfloat16 g_oh[MKELEM], g_ol[MKELEM];  // [row][512]
__device__ uint32_t g_mbits[BB*64*SS];                      // [b][kchunk][q]

// ---------------- PTX helpers ----------------
__device__ __forceinline__ uint32_t smem_u32(const void* p) {
    uint32_t a;
    asm("{ .reg .u64 t; cvta.to.shared.u64 t, %1; cvt.u32.u64 %0, t; }" : "=r"(a) : "l"(p));
    return a;
}
#define CP16(dst, src) \
    asm volatile("cp.async.cg.shared.global [%0], [%1], 16;" :: "r"(dst), "l"(src))
#define CPCOMMIT() asm volatile("cp.async.commit_group;" ::: "memory")
#define CPWAIT(n)  asm volatile("cp.async.wait_group %0;" :: "n"(n) : "memory")

#define LDSM4(d0,d1,d2,d3,a) \
    asm volatile("ldmatrix.sync.aligned.m8n8.x4.shared.b16 {%0,%1,%2,%3},[%4];" \
        : "=r"(d0),"=r"(d1),"=r"(d2),"=r"(d3) : "r"(a))
#define LDSM4T(d0,d1,d2,d3,a) \
    asm volatile("ldmatrix.sync.aligned.m8n8.x4.trans.shared.b16 {%0,%1,%2,%3},[%4];" \
        : "=r"(d0),"=r"(d1),"=r"(d2),"=r"(d3) : "r"(a))
#define LDSM2(d0,d1,a) \
    asm volatile("ldmatrix.sync.aligned.m8n8.x2.shared.b16 {%0,%1},[%2];" \
        : "=r"(d0),"=r"(d1) : "r"(a))

__device__ __forceinline__ void mma16816(float* d,
    uint32_t a0, uint32_t a1, uint32_t a2, uint32_t a3, uint32_t b0, uint32_t b1)
{
    asm volatile(
        "mma.sync.aligned.m16n8k16.row.col.f32.bf16.bf16.f32 "
        "{%0,%1,%2,%3},{%4,%5,%6,%7},{%8,%9},{%0,%1,%2,%3};"
        : "+f"(d[0]), "+f"(d[1]), "+f"(d[2]), "+f"(d[3])
        : "r"(a0), "r"(a1), "r"(a2), "r"(a3), "r"(b0), "r"(b1));
}

__device__ __forceinline__ uint32_t packbf(float x0, float x1) {
    __nv_bfloat162 t = __floats2bfloat162_rn(x0, x1);
    return reinterpret_cast<uint32_t&>(t);
}
__device__ __forceinline__ uint32_t packres(float x0, float x1, uint32_t h) {
    float f0 = __uint_as_float(h << 16);
    float f1 = __uint_as_float(h & 0xffff0000u);
    return packbf(x0 - f0, x1 - f1);
}
__device__ __forceinline__ void split1(float x, __nv_bfloat16& h, __nv_bfloat16& l) {
    h = __float2bfloat16(x);
    l = __float2bfloat16(x - __bfloat162float(h));
}

// ============================================================================
// activation split
// ============================================================================
__global__ void split_act_kernel(const float* __restrict__ s0, const float* __restrict__ s1,
                                 const float* __restrict__ s2) {
    const int z = blockIdx.z;
    const float* src = (z == 0) ? s0 : (z == 1) ? s1 : s2;
    __nv_bfloat16* hi = g_act_hi + (size_t)z * MKELEM;
    __nv_bfloat16* lo = g_act_lo + (size_t)z * MKELEM;
    size_t idx = (size_t)blockIdx.x * blockDim.x + threadIdx.x;
    float4 v = ((const float4*)src)[idx];
    __nv_bfloat16 h0, h1, h2, h3, l0, l1, l2, l3;
    split1(v.x, h0, l0); split1(v.y, h1, l1); split1(v.z, h2, l2); split1(v.w, h3, l3);
    ((__nv_bfloat162*)hi)[idx*2+0] = __halves2bfloat162(h0, h1);
    ((__nv_bfloat162*)hi)[idx*2+1] = __halves2bfloat162(h2, h3);
    ((__nv_bfloat162*)lo)[idx*2+0] = __halves2bfloat162(l0, l1);
    ((__nv_bfloat162*)lo)[idx*2+1] = __halves2bfloat162(l2, l3);
}

// ============================================================================
// weight transpose + split
// ============================================================================
__global__ void wsplit_kernel(const float* __restrict__ wq, const float* __restrict__ wk,
                              const float* __restrict__ wv, const float* __restrict__ wo) {
    __shared__ float t[32][33];
    const int z = blockIdx.z;
    const float* W = (z == 0) ? wq : (z == 1) ? wk : (z == 2) ? wv : wo;
    const int n0 = blockIdx.x * 32, k0 = blockIdx.y * 32;
    const int tx = threadIdx.x, ty = threadIdx.y;
#pragma unroll
    for (int i = 0; i < 32; i += 8) t[ty+i][tx] = W[(size_t)(k0+ty+i)*512 + n0 + tx];
    __syncthreads();
    __nv_bfloat16* Hi = g_wt_hi + (size_t)z * KNELEM;
    __nv_bfloat16* Lo = g_wt_lo + (size_t)z * KNELEM;
#pragma unroll
    for (int i = 0; i < 32; i += 8) {
        float x = t[tx][ty+i];
        __nv_bfloat16 h, l; split1(x, h, l);
        Hi[(size_t)(n0+ty+i)*512 + k0 + tx] = h;
        Lo[(size_t)(n0+ty+i)*512 + k0 + tx] = l;
    }
}

// ============================================================================
// mask -> bit pack
// ============================================================================
__global__ void maskpack_kernel(const int* __restrict__ mask) {
    int wid = blockIdx.x * 8 + (threadIdx.x >> 5);
    int lane = threadIdx.x & 31;
    int kc = wid & 63;
    int q  = (wid >> 6) & 2047;
    int b  = wid >> 17;
    int v = mask[((size_t)b*SS + q)*SS + kc*32 + lane];
    uint32_t bits = __ballot_sync(0xffffffffu, v != 0);
    if (lane == 0) g_mbits[((size_t)b*64 + kc)*SS + q] = bits;
}

// ============================================================================
// GEMM via mma.sync + ldmatrix + cp.async double buffer.
// Block 128x128, 8 warps (4m x 2n), warp 32x64. K-chunks of 32, 16 chunks.
// Stage layout (bytes): Ah@0 Al@10240 Bh@20480 Bl@30720, stride 40 elems.
// ============================================================================
#define G_STRIDE 40
#define G_ARR    10240
#define G_STAGE  40960
#define G_SMEM   (2*G_STAGE)

__global__ __launch_bounds__(256, 2) void gemm_mma_kernel(
    int phase, const float* __restrict__ bq, const float* __restrict__ bk,
    const float* __restrict__ bv, float* __restrict__ outp)
{
    extern __shared__ char smc[];
    const uint32_t sb = smem_u32(smc);

    const int tid = threadIdx.x;
    const int w = tid >> 5, lane = tid & 31;
    const int g = lane >> 2, t2 = (lane & 3) * 2;
    const int z = blockIdx.z;
    const int n0 = blockIdx.x * 128, m0 = blockIdx.y * 128;
    const int wr = (w & 3) * 32, wc = (w >> 2) * 64;

    const __nv_bfloat16 *Ah, *Al, *Bh, *Bl;
    const float* bias;
    if (phase == 0) {
        Ah = g_act_hi + (size_t)z * MKELEM; Al = g_act_lo + (size_t)z * MKELEM;
        Bh = g_wt_hi + (size_t)z * KNELEM;  Bl = g_wt_lo + (size_t)z * KNELEM;
        bias = (z == 0) ? bq : (z == 1) ? bk : bv;
    } else {
        Ah = g_oh; Al = g_ol;
        Bh = g_wt_hi + (size_t)3 * KNELEM; Bl = g_wt_lo + (size_t)3 * KNELEM;
        bias = bq;
    }

    // staging: 2 chunks of 16B per array per thread
    const int r0c = (tid*2) >> 2, c0c = ((tid*2) & 3) * 8;
    const int r1c = (tid*2+1) >> 2, c1c = ((tid*2+1) & 3) * 8;
    const uint32_t d0off = (uint32_t)(r0c*G_STRIDE + c0c) * 2;
    const uint32_t d1off = (uint32_t)(r1c*G_STRIDE + c1c) * 2;

    // fragment lane offsets (bytes)
    const uint32_t aLane = ((uint32_t)((lane & 15))*G_STRIDE + (lane >> 4)*8) * 2;
    const uint32_t bLane = ((uint32_t)(wc + (lane & 7))*G_STRIDE + ((lane >> 3) & 1)*8) * 2;

    float dacc[2][8][4];
#pragma unroll
    for (int mi = 0; mi < 2; mi++)
#pragma unroll
        for (int j = 0; j < 8; j++)
#pragma unroll
            for (int c = 0; c < 4; c++) dacc[mi][j][c] = 0.f;

    auto issue = [&](int kc) {
        const uint32_t st = sb + (kc & 1) * G_STAGE;
        const size_t ga0 = (size_t)(m0 + r0c)*512 + kc*32 + c0c;
        const size_t ga1 = (size_t)(m0 + r1c)*512 + kc*32 + c1c;
        const size_t gb0 = (size_t)(n0 + r0c)*512 + kc*32 + c0c;
        const size_t gb1 = (size_t)(n0 + r1c)*512 + kc*32 + c1c;
        CP16(st + 0*G_ARR + d0off, Ah + ga0);  CP16(st + 0*G_ARR + d1off, Ah + ga1);
        CP16(st + 1*G_ARR + d0off, Al + ga0);  CP16(st + 1*G_ARR + d1off, Al + ga1);
        CP16(st + 2*G_ARR + d0off, Bh + gb0);  CP16(st + 2*G_ARR + d1off, Bh + gb1);
        CP16(st + 3*G_ARR + d0off, Bl + gb0);  CP16(st + 3*G_ARR + d1off, Bl + gb1);
    };

    issue(0); CPCOMMIT();

    for (int kc = 0; kc < 16; kc++) {
        __syncthreads();
        if (kc < 15) { issue(kc+1); CPCOMMIT(); CPWAIT(1); }
        else         { CPWAIT(0); }
        __syncthreads();

        const uint32_t st = sb + (kc & 1) * G_STAGE;
        const uint32_t aH = st, aL = st + G_ARR, bH = st + 2*G_ARR, bL = st + 3*G_ARR;

#pragma unroll
        for (int ks = 0; ks < 2; ks++) {
            const uint32_t ko = (uint32_t)(ks*16) * 2;
            uint32_t ahf[2][4], alf[2][4];
#pragma unroll
            for (int mi = 0; mi < 2; mi++) {
                const uint32_t ro = (uint32_t)((wr + mi*16)*G_STRIDE) * 2;
                LDSM4(ahf[mi][0], ahf[mi][1], ahf[mi][2], ahf[mi][3], aH + ro + aLane + ko);
                LDSM4(alf[mi][0], alf[mi][1], alf[mi][2], alf[mi][3], aL + ro + aLane + ko);
            }
#pragma unroll
            for (int j = 0; j < 8; j++) {
                const uint32_t jo = (uint32_t)(8*j*G_STRIDE) * 2;
                uint32_t bh0, bh1, bl0, bl1;
                LDSM2(bh0, bh1, bH + jo + bLane + ko);
                LDSM2(bl0, bl1, bL + jo + bLane + ko);
#pragma unroll
                for (int mi = 0; mi < 2; mi++) {
                    mma16816(dacc[mi][j], ahf[mi][0], ahf[mi][1], ahf[mi][2], ahf[mi][3], bh0, bh1);
                    mma16816(dacc[mi][j], ahf[mi][0], ahf[mi][1], ahf[mi][2], ahf[mi][3], bl0, bl1);
                    mma16816(dacc[mi][j], alf[mi][0], alf[mi][1], alf[mi][2], alf[mi][3], bh0, bh1);
                }
            }
        }
    }

    // epilogue
    __nv_bfloat16 *oh = nullptr, *ol = nullptr;
    if (phase == 0) {
        oh = (z == 0) ? g_qh : (z == 1) ? g_kh : g_vh;
        ol = (z == 0) ? g_ql : (z == 1) ? g_kl : g_vl;
    }
#pragma unroll
    for (int mi = 0; mi < 2; mi++) {
        const int r0 = m0 + wr + mi*16 + g;
#pragma unroll
        for (int j = 0; j < 8; j++) {
            const int col = n0 + wc + 8*j + t2;
            float2 bs = *(const float2*)(bias + col);
            float v0 = dacc[mi][j][0] + bs.x, v1 = dacc[mi][j][1] + bs.y;
            float v2 = dacc[mi][j][2] + bs.x, v3 = dacc[mi][j][3] + bs.y;
            if (phase == 1) {
                *(float2*)(outp + (size_t)r0*512 + col) = make_float2(v0, v1);
                *(float2*)(outp + (size_t)(r0+8)*512 + col) = make_float2(v2, v3);
            } else {
                const int bidx = r0 >> 11, s = r0 & 2047;
                const int hh = col >> 6, d = col & 63;
                size_t o0 = ((size_t)(bidx*HH + hh)*SS + s)*64 + d;
                size_t o8 = o0 + 8*64;
                uint32_t h0 = packbf(v0, v1);
                *(uint32_t*)(oh + o0) = h0;
                *(uint32_t*)(ol + o0) = packres(v0, v1, h0);
                uint32_t h8 = packbf(v2, v3);
                *(uint32_t*)(oh + o8) = h8;
                *(uint32_t*)(ol + o8) = packres(v2, v3, h8);
            }
        }
    }
}

// ============================================================================
// Flash attention: ldmatrix (+trans for V) + cp.async double buffer.
// Block=(h, 128 q-rows, b), 8 warps, warp owns 16 q-rows.
// Stage (bytes): Kh@0 Kl@9216 Vh@18432 Vl@27648, rows [s][d] stride 72.
// ============================================================================
#define A_STRIDE 72
#define A_ARR    9216
#define A_STAGE  36864
#define A_SMEM   (2*A_STAGE)

__global__ __launch_bounds__(256) void attn_kernel()
{
    extern __shared__ char smc[];
    const uint32_t sb = smem_u32(smc);

    const int tid = threadIdx.x;
    const int w = tid >> 5, lane = tid & 31;
    const int g = lane >> 2, t2 = (lane & 3) * 2;
    const int h = blockIdx.x, q0 = blockIdx.y * 128, b = blockIdx.z;
    const int mr = w * 16;
    const size_t bh = (size_t)(b*HH + h) * SS;

    // staging: 2 chunks per array per thread (64 rows x 8 chunks = 512)
    const int r0c = (tid*2) >> 3, c0c = ((tid*2) & 7) * 8;
    const int r1c = (tid*2+1) >> 3, c1c = ((tid*2+1) & 7) * 8;
    const uint32_t d0off = (uint32_t)(r0c*A_STRIDE + c0c) * 2;
    const uint32_t d1off = (uint32_t)(r1c*A_STRIDE + c1c) * 2;

    // fragment lane offsets (bytes)
    const uint32_t kLane = ((uint32_t)(lane & 7)*A_STRIDE + (lane >> 3)*8) * 2;  // K: n-rows=s
    const uint32_t vLane = (uint32_t)lane * A_STRIDE * 2;                        // V trans: rows=s

    // ---- Q fragments, register-resident ----
    uint32_t qhf[4][4], qlf[4][4];
    {
        const __nv_bfloat16* qh = g_qh + (bh + q0 + mr) * DD;
        const __nv_bfloat16* ql = g_ql + (bh + q0 + mr) * DD;
#pragma unroll
        for (int kk = 0; kk < 4; kk++) {
            const int kb = kk*16 + t2;
            qhf[kk][0] = *(const uint32_t*)(qh + g*64 + kb);
            qhf[kk][1] = *(const uint32_t*)(qh + (g+8)*64 + kb);
            qhf[kk][2] = *(const uint32_t*)(qh + g*64 + kb + 8);
            qhf[kk][3] = *(const uint32_t*)(qh + (g+8)*64 + kb + 8);
            qlf[kk][0] = *(const uint32_t*)(ql + g*64 + kb);
            qlf[kk][1] = *(const uint32_t*)(ql + (g+8)*64 + kb);
            qlf[kk][2] = *(const uint32_t*)(ql + g*64 + kb + 8);
            qlf[kk][3] = *(const uint32_t*)(ql + (g+8)*64 + kb + 8);
        }
    }

    float oacc[8][4];
#pragma unroll
    for (int j = 0; j < 8; j++)
#pragma unroll
        for (int c = 0; c < 4; c++) oacc[j][c] = 0.f;
    float m0 = __int_as_float(0xff800000), m1 = m0;
    float l0 = 0.f, l1 = 0.f;

    auto issue = [&](int kt) {
        const uint32_t st = sb + (kt & 1) * A_STAGE;
        const size_t s0 = (bh + kt*64 + r0c) * 64 + c0c;
        const size_t s1 = (bh + kt*64 + r1c) * 64 + c1c;
        CP16(st + 0*A_ARR + d0off, g_kh + s0);  CP16(st + 0*A_ARR + d1off, g_kh + s1);
        CP16(st + 1*A_ARR + d0off, g_kl + s0);  CP16(st + 1*A_ARR + d1off, g_kl + s1);
        CP16(st + 2*A_ARR + d0off, g_vh + s0);  CP16(st + 2*A_ARR + d1off, g_vh + s1);
        CP16(st + 3*A_ARR + d0off, g_vl + s0);  CP16(st + 3*A_ARR + d1off, g_vl + s1);
    };

    issue(0); CPCOMMIT();

    for (int kt = 0; kt < 32; kt++) {
        __syncthreads();
        if (kt < 31) { issue(kt+1); CPCOMMIT(); CPWAIT(1); }
        else         { CPWAIT(0); }
        __syncthreads();

        const uint32_t st = sb + (kt & 1) * A_STAGE;
        const uint32_t kH = st, kL = st + A_ARR, vH = st + 2*A_ARR, vL = st + 3*A_ARR;

        // ---- scores: S = Q K^T (3-pass) ----
        float sacc[8][4];
#pragma unroll
        for (int j = 0; j < 8; j++)
#pragma unroll
            for (int c = 0; c < 4; c++) sacc[j][c] = 0.f;

#pragma unroll
        for (int j = 0; j < 8; j++) {
            const uint32_t jo = (uint32_t)(8*j*A_STRIDE) * 2;
            uint32_t bhR[8], blR[8];
            LDSM4(bhR[0], bhR[1], bhR[2], bhR[3], kH + jo + kLane);
            LDSM4(bhR[4], bhR[5], bhR[6], bhR[7], kH + jo + kLane + 64);
            LDSM4(blR[0], blR[1], blR[2], blR[3], kL + jo + kLane);
            LDSM4(blR[4], blR[5], blR[6], blR[7], kL + jo + kLane + 64);
#pragma unroll
            for (int kk = 0; kk < 4; kk++) {
                mma16816(sacc[j], qhf[kk][0], qhf[kk][1], qhf[kk][2], qhf[kk][3], bhR[2*kk], bhR[2*kk+1]);
                mma16816(sacc[j], qhf[kk][0], qhf[kk][1], qhf[kk][2], qhf[kk][3], blR[2*kk], blR[2*kk+1]);
                mma16816(sacc[j], qlf[kk][0], qlf[kk][1], qlf[kk][2], qlf[kk][3], bhR[2*kk], bhR[2*kk+1]);
            }
        }

        // ---- mask + scale (direct LDG, L1-resident) ----
        const size_t mrow = ((size_t)b*64 + (kt*64 >> 5))*SS + q0;
        const uint32_t mwa0 = g_mbits[mrow + mr + g];
        const uint32_t mwa1 = g_mbits[mrow + SS + mr + g];
        const uint32_t mwb0 = g_mbits[mrow + mr + g + 8];
        const uint32_t mwb1 = g_mbits[mrow + SS + mr + g + 8];
#pragma unroll
        for (int j = 0; j < 8; j++) {
            const int sh = (j & 3)*8 + t2;
            const uint32_t wa = (j < 4) ? mwa0 : mwa1;
            const uint32_t wb = (j < 4) ? mwb0 : mwb1;
            sacc[j][0] = (((wa >> sh) & 1)     ? sacc[j][0] : -1e9f) * 0.125f;
            sacc[j][1] = (((wa >> (sh+1)) & 1) ? sacc[j][1] : -1e9f) * 0.125f;
            sacc[j][2] = (((wb >> sh) & 1)     ? sacc[j][2] : -1e9f) * 0.125f;
            sacc[j][3] = (((wb >> (sh+1)) & 1) ? sacc[j][3] : -1e9f) * 0.125f;
        }

        // ---- online softmax ----
        float mx0 = sacc[0][0], mx1 = sacc[0][2];
#pragma unroll
        for (int j = 0; j < 8; j++) {
            mx0 = fmaxf(mx0, fmaxf(sacc[j][0], sacc[j][1]));
            mx1 = fmaxf(mx1, fmaxf(sacc[j][2], sacc[j][3]));
        }
#pragma unroll
        for (int o = 1; o <= 2; o <<= 1) {
            mx0 = fmaxf(mx0, __shfl_xor_sync(0xffffffffu, mx0, o));
            mx1 = fmaxf(mx1, __shfl_xor_sync(0xffffffffu, mx1, o));
        }
        const float nm0 = fmaxf(m0, mx0), nm1 = fmaxf(m1, mx1);
        const float cr0 = __expf(m0 - nm0), cr1 = __expf(m1 - nm1);
        m0 = nm0; m1 = nm1;

        float rs0 = 0.f, rs1 = 0.f;
#pragma unroll
        for (int j = 0; j < 8; j++) {
            sacc[j][0] = __expf(sacc[j][0] - nm0);
            sacc[j][1] = __expf(sacc[j][1] - nm0);
            sacc[j][2] = __expf(sacc[j][2] - nm1);
            sacc[j][3] = __expf(sacc[j][3] - nm1);
            rs0 += sacc[j][0] + sacc[j][1];
            rs1 += sacc[j][2] + sacc[j][3];
        }
#pragma unroll
        for (int o = 1; o <= 2; o <<= 1) {
            rs0 += __shfl_xor_sync(0xffffffffu, rs0, o);
            rs1 += __shfl_xor_sync(0xffffffffu, rs1, o);
        }
        l0 = l0 * cr0 + rs0;
        l1 = l1 * cr1 + rs1;
#pragma unroll
        for (int j = 0; j < 8; j++) {
            oacc[j][0] *= cr0; oacc[j][1] *= cr0;
            oacc[j][2] *= cr1; oacc[j][3] *= cr1;
        }

        // ---- pack P fragments (hi + residual lo) in registers ----
        uint32_t pah[4][4], pal[4][4];
#pragma unroll
        for (int kk = 0; kk < 4; kk++) {
            const int j0 = 2*kk, j1 = 2*kk + 1;
            pah[kk][0] = packbf(sacc[j0][0], sacc[j0][1]);
            pah[kk][1] = packbf(sacc[j0][2], sacc[j0][3]);
            pah[kk][2] = packbf(sacc[j1][0], sacc[j1][1]);
            pah[kk][3] = packbf(sacc[j1][2], sacc[j1][3]);
            pal[kk][0] = packres(sacc[j0][0], sacc[j0][1], pah[kk][0]);
            pal[kk][1] = packres(sacc[j0][2], sacc[j0][3], pah[kk][1]);
            pal[kk][2] = packres(sacc[j1][0], sacc[j1][1], pah[kk][2]);
            pal[kk][3] = packres(sacc[j1][2], sacc[j1][3], pah[kk][3]);
        }

        // ---- PV: O += P V (3-pass, V via ldmatrix.trans) ----
#pragma unroll
        for (int j2 = 0; j2 < 8; j2++) {
            const uint32_t jo = (uint32_t)(8*j2) * 2;
            uint32_t vhR[8], vlR[8];
            LDSM4T(vhR[0], vhR[1], vhR[2], vhR[3], vH + vLane + jo);
            LDSM4T(vhR[4], vhR[5], vhR[6], vhR[7], vH + vLane + jo + 32*A_STRIDE*2);
            LDSM4T(vlR[0], vlR[1], vlR[2], vlR[3], vL + vLane + jo);
            LDSM4T(vlR[4], vlR[5], vlR[6], vlR[7], vL + vLane + jo + 32*A_STRIDE*2);
#pragma unroll
            for (int kk = 0; kk < 4; kk++) {
                mma16816(oacc[j2], pah[kk][0], pah[kk][1], pah[kk][2], pah[kk][3], vhR[2*kk], vhR[2*kk+1]);
                mma16816(oacc[j2], pah[kk][0], pah[kk][1], pah[kk][2], pah[kk][3], vlR[2*kk], vlR[2*kk+1]);
                mma16816(oacc[j2], pal[kk][0], pal[kk][1], pal[kk][2], pal[kk][3], vhR[2*kk], vhR[2*kk+1]);
            }
        }
    }

    // ---- epilogue ----
    const float inv0 = 1.f / l0, inv1 = 1.f / l1;
    const size_t row0 = (size_t)b*SS + q0 + mr + g;
#pragma unroll
    for (int j2 = 0; j2 < 8; j2++) {
        const int d = 8*j2 + t2;
        float v0 = oacc[j2][0] * inv0, v1 = oacc[j2][1] * inv0;
        float v2 = oacc[j2][2] * inv1, v3 = oacc[j2][3] * inv1;
        uint32_t h0 = packbf(v0, v1);
        *(uint32_t*)(g_oh + row0*512 + h*64 + d) = h0;
        *(uint32_t*)(g_ol + row0*512 + h*64 + d) = packres(v0, v1, h0);
        uint32_t h8 = packbf(v2, v3);
        *(uint32_t*)(g_oh + (row0+8)*512 + h*64 + d) = h8;
        *(uint32_t*)(g_ol + (row0+8)*512 + h*64 + d) = packres(v2, v3, h8);
    }
}

// ============================================================================
extern "C" void kernel_launch(void* const* d_in, const int* in_sizes, int n_in,
                              void* d_out, int out_size)
{
    const float* iq   = (const float*)d_in[0];
    const float* ik   = (const float*)d_in[1];
    const float* iv   = (const float*)d_in[2];
    const int*   mask = (const int*)  d_in[3];
    const float* wq   = (const float*)d_in[4];
    const float* bq   = (const float*)d_in[5];
    const float* wk   = (const float*)d_in[6];
    const float* bk   = (const float*)d_in[7];
    const float* wv   = (const float*)d_in[8];
    const float* bv   = (const float*)d_in[9];
    const float* wo   = (const float*)d_in[10];
    const float* bo   = (const float*)d_in[11];
    float* out = (float*)d_out;

    cudaFuncSetAttribute(gemm_mma_kernel, cudaFuncAttributeMaxDynamicSharedMemorySize, G_SMEM);
    cudaFuncSetAttribute(attn_kernel, cudaFuncAttributeMaxDynamicSharedMemorySize, A_SMEM);

    split_act_kernel<<<dim3(MKELEM/4/256, 1, 3), 256>>>(iq, ik, iv);
    wsplit_kernel<<<dim3(16, 16, 4), dim3(32, 8)>>>(wq, wk, wv, wo);
    maskpack_kernel<<<BB*SS*64/8, 256>>>(mask);
    gemm_mma_kernel<<<dim3(4, 64, 3), 256, G_SMEM>>>(0, bq, bk, bv, nullptr);
    attn_kernel<<<dim3(HH, SS/128, BB), 256, A_SMEM>>>();
    gemm_mma_kernel<<<dim3(4, 64, 1), 256, G_SMEM>>>(1, bo, nullptr, nullptr, out);
}

// round 5
// speedup vs baseline: 2.4425x; 1.0934x over previous
#include <cuda_runtime.h>
#include <cuda_bf16.h>
#include <stdint.h>

// ---------------- problem constants ----------------
#define BB 4
#define SS 2048
#define HH 8
#define DD 64
#define MKELEM (8192*512)
#define KNELEM (512*512)
#define BHSD (BB*HH*SS*DD)

// ---------------- scratch (__device__ globals, allocation-free) ----------------
__device__ __align__(16) __nv_bfloat16 g_act_hi[3*MKELEM];
__device__ __align__(16) __nv_bfloat16 g_act_lo[3*MKELEM];
__device__ __align__(16) __nv_bfloat16 g_wt_hi[4*KNELEM];   // transposed [n][k]
__device__ __align__(16) __nv_bfloat16 g_wt_lo[4*KNELEM];
__device__ __align__(16) __nv_bfloat16 g_qh[BHSD], g_ql[BHSD];   // [b,h,s,d]
__device__ __align__(16) __nv_bfloat16 g_kh[BHSD], g_kl[BHSD];
__device__ __align__(16) __nv_bfloat16 g_vh[BHSD], g_vl[BHSD];
__device__ __align__(16) __nv_bfloat16 g_oh[MKELEM], g_ol[MKELEM];  // [row][512]
__device__ uint32_t g_mbits[BB*64*SS];                      // [b][kchunk][q]

// ---------------- PTX helpers ----------------
__device__ __forceinline__ uint32_t smem_u32(const void* p) {
    uint32_t a;
    asm("{ .reg .u64 t; cvta.to.shared.u64 t, %1; cvt.u32.u64 %0, t; }" : "=r"(a) : "l"(p));
    return a;
}
#define CP16(dst, src) \
    asm volatile("cp.async.cg.shared.global [%0], [%1], 16;" :: "r"(dst), "l"(src))
#define CPCOMMIT() asm volatile("cp.async.commit_group;" ::: "memory")
#define CPWAIT(n)  asm volatile("cp.async.wait_group %0;" :: "n"(n) : "memory")

#define LDSM4(d0,d1,d2,d3,a) \
    asm volatile("ldmatrix.sync.aligned.m8n8.x4.shared.b16 {%0,%1,%2,%3},[%4];" \
        : "=r"(d0),"=r"(d1),"=r"(d2),"=r"(d3) : "r"(a))
#define LDSM4T(d0,d1,d2,d3,a) \
    asm volatile("ldmatrix.sync.aligned.m8n8.x4.trans.shared.b16 {%0,%1,%2,%3},[%4];" \
        : "=r"(d0),"=r"(d1),"=r"(d2),"=r"(d3) : "r"(a))

__device__ __forceinline__ void mma16816(float* d,
    uint32_t a0, uint32_t a1, uint32_t a2, uint32_t a3, uint32_t b0, uint32_t b1)
{
    asm volatile(
        "mma.sync.aligned.m16n8k16.row.col.f32.bf16.bf16.f32 "
        "{%0,%1,%2,%3},{%4,%5,%6,%7},{%8,%9},{%0,%1,%2,%3};"
        : "+f"(d[0]), "+f"(d[1]), "+f"(d[2]), "+f"(d[3])
        : "r"(a0), "r"(a1), "r"(a2), "r"(a3), "r"(b0), "r"(b1));
}

__device__ __forceinline__ uint32_t packbf(float x0, float x1) {
    __nv_bfloat162 t = __floats2bfloat162_rn(x0, x1);
    return reinterpret_cast<uint32_t&>(t);
}
__device__ __forceinline__ uint32_t packres(float x0, float x1, uint32_t h) {
    float f0 = __uint_as_float(h << 16);
    float f1 = __uint_as_float(h & 0xffff0000u);
    return packbf(x0 - f0, x1 - f1);
}
__device__ __forceinline__ void split1(float x, __nv_bfloat16& h, __nv_bfloat16& l) {
    h = __float2bfloat16(x);
    l = __float2bfloat16(x - __bfloat162float(h));
}

// ============================================================================
// activation split
// ============================================================================
__global__ void split_act_kernel(const float* __restrict__ s0, const float* __restrict__ s1,
                                 const float* __restrict__ s2) {
    const int z = blockIdx.z;
    const float* src = (z == 0) ? s0 : (z == 1) ? s1 : s2;
    __nv_bfloat16* hi = g_act_hi + (size_t)z * MKELEM;
    __nv_bfloat16* lo = g_act_lo + (size_t)z * MKELEM;
    size_t idx = (size_t)blockIdx.x * blockDim.x + threadIdx.x;
    float4 v = ((const float4*)src)[idx];
    __nv_bfloat16 h0, h1, h2, h3, l0, l1, l2, l3;
    split1(v.x, h0, l0); split1(v.y, h1, l1); split1(v.z, h2, l2); split1(v.w, h3, l3);
    ((__nv_bfloat162*)hi)[idx*2+0] = __halves2bfloat162(h0, h1);
    ((__nv_bfloat162*)hi)[idx*2+1] = __halves2bfloat162(h2, h3);
    ((__nv_bfloat162*)lo)[idx*2+0] = __halves2bfloat162(l0, l1);
    ((__nv_bfloat162*)lo)[idx*2+1] = __halves2bfloat162(l2, l3);
}

// ============================================================================
// weight transpose + split
// ============================================================================
__global__ void wsplit_kernel(const float* __restrict__ wq, const float* __restrict__ wk,
                              const float* __restrict__ wv, const float* __restrict__ wo) {
    __shared__ float t[32][33];
    const int z = blockIdx.z;
    const float* W = (z == 0) ? wq : (z == 1) ? wk : (z == 2) ? wv : wo;
    const int n0 = blockIdx.x * 32, k0 = blockIdx.y * 32;
    const int tx = threadIdx.x, ty = threadIdx.y;
#pragma unroll
    for (int i = 0; i < 32; i += 8) t[ty+i][tx] = W[(size_t)(k0+ty+i)*512 + n0 + tx];
    __syncthreads();
    __nv_bfloat16* Hi = g_wt_hi + (size_t)z * KNELEM;
    __nv_bfloat16* Lo = g_wt_lo + (size_t)z * KNELEM;
#pragma unroll
    for (int i = 0; i < 32; i += 8) {
        float x = t[tx][ty+i];
        __nv_bfloat16 h, l; split1(x, h, l);
        Hi[(size_t)(n0+ty+i)*512 + k0 + tx] = h;
        Lo[(size_t)(n0+ty+i)*512 + k0 + tx] = l;
    }
}

// ============================================================================
// mask -> bit pack
// ============================================================================
__global__ void maskpack_kernel(const int* __restrict__ mask) {
    int wid = blockIdx.x * 8 + (threadIdx.x >> 5);
    int lane = threadIdx.x & 31;
    int kc = wid & 63;
    int q  = (wid >> 6) & 2047;
    int b  = wid >> 17;
    int v = mask[((size_t)b*SS + q)*SS + kc*32 + lane];
    uint32_t bits = __ballot_sync(0xffffffffu, v != 0);
    if (lane == 0) g_mbits[((size_t)b*64 + kc)*SS + q] = bits;
}

// ============================================================================
// GEMM: mma.sync + ldmatrix + cp.async, 2-stage, ONE barrier per k-chunk.
// Block 128x128, 8 warps (4m x 2n), warp 32x64. K-chunks of 32, 16 chunks.
// ============================================================================
#define G_STRIDE 40
#define G_ARR    10240
#define G_STAGE  40960
#define G_SMEM   (2*G_STAGE)

__global__ __launch_bounds__(256, 2) void gemm_mma_kernel(
    int phase, const float* __restrict__ bq, const float* __restrict__ bk,
    const float* __restrict__ bv, float* __restrict__ outp)
{
    extern __shared__ char smc[];
    const uint32_t sb = smem_u32(smc);

    const int tid = threadIdx.x;
    const int w = tid >> 5, lane = tid & 31;
    const int g = lane >> 2, t2 = (lane & 3) * 2;
    const int z = blockIdx.z;
    const int n0 = blockIdx.x * 128, m0 = blockIdx.y * 128;
    const int wr = (w & 3) * 32, wc = (w >> 2) * 64;

    const __nv_bfloat16 *Ah, *Al, *Bh, *Bl;
    const float* bias;
    if (phase == 0) {
        Ah = g_act_hi + (size_t)z * MKELEM; Al = g_act_lo + (size_t)z * MKELEM;
        Bh = g_wt_hi + (size_t)z * KNELEM;  Bl = g_wt_lo + (size_t)z * KNELEM;
        bias = (z == 0) ? bq : (z == 1) ? bk : bv;
    } else {
        Ah = g_oh; Al = g_ol;
        Bh = g_wt_hi + (size_t)3 * KNELEM; Bl = g_wt_lo + (size_t)3 * KNELEM;
        bias = bq;
    }

    // staging: 2 chunks of 16B per array per thread
    const int r0c = (tid*2) >> 2, c0c = ((tid*2) & 3) * 8;
    const int r1c = (tid*2+1) >> 2, c1c = ((tid*2+1) & 3) * 8;
    const uint32_t d0off = (uint32_t)(r0c*G_STRIDE + c0c) * 2;
    const uint32_t d1off = (uint32_t)(r1c*G_STRIDE + c1c) * 2;

    // fragment lane offsets (bytes): A rows m, B rows n (16-row x4 pattern)
    const uint32_t aLane = ((uint32_t)(lane & 15)*G_STRIDE + (lane >> 4)*8) * 2;
    const uint32_t bLane = ((uint32_t)(wc + (lane & 15))*G_STRIDE + (lane >> 4)*8) * 2;

    float dacc[2][8][4];
#pragma unroll
    for (int mi = 0; mi < 2; mi++)
#pragma unroll
        for (int j = 0; j < 8; j++)
#pragma unroll
            for (int c = 0; c < 4; c++) dacc[mi][j][c] = 0.f;

    auto issue = [&](int kc) {
        const uint32_t st = sb + (kc & 1) * G_STAGE;
        const size_t ga0 = (size_t)(m0 + r0c)*512 + kc*32 + c0c;
        const size_t ga1 = (size_t)(m0 + r1c)*512 + kc*32 + c1c;
        const size_t gb0 = (size_t)(n0 + r0c)*512 + kc*32 + c0c;
        const size_t gb1 = (size_t)(n0 + r1c)*512 + kc*32 + c1c;
        CP16(st + 0*G_ARR + d0off, Ah + ga0);  CP16(st + 0*G_ARR + d1off, Ah + ga1);
        CP16(st + 1*G_ARR + d0off, Al + ga0);  CP16(st + 1*G_ARR + d1off, Al + ga1);
        CP16(st + 2*G_ARR + d0off, Bh + gb0);  CP16(st + 2*G_ARR + d1off, Bh + gb1);
        CP16(st + 3*G_ARR + d0off, Bl + gb0);  CP16(st + 3*G_ARR + d1off, Bl + gb1);
    };

    issue(0); CPCOMMIT();

    for (int kc = 0; kc < 16; kc++) {
        CPWAIT(0);
        __syncthreads();            // stage kc published; stage kc^1 free (read at kc-1)
        if (kc < 15) { issue(kc+1); CPCOMMIT(); }

        const uint32_t st = sb + (kc & 1) * G_STAGE;
        const uint32_t aH = st, aL = st + G_ARR, bH = st + 2*G_ARR, bL = st + 3*G_ARR;

#pragma unroll
        for (int ks = 0; ks < 2; ks++) {
            const uint32_t ko = (uint32_t)(ks*16) * 2;
            uint32_t ahf[2][4], alf[2][4];
#pragma unroll
            for (int mi = 0; mi < 2; mi++) {
                const uint32_t ro = (uint32_t)((wr + mi*16)*G_STRIDE) * 2;
                LDSM4(ahf[mi][0], ahf[mi][1], ahf[mi][2], ahf[mi][3], aH + ro + aLane + ko);
                LDSM4(alf[mi][0], alf[mi][1], alf[mi][2], alf[mi][3], aL + ro + aLane + ko);
            }
#pragma unroll
            for (int jp = 0; jp < 4; jp++) {     // j-pairs via 16-row LDSM4
                const uint32_t jo = (uint32_t)(16*jp*G_STRIDE) * 2;
                uint32_t bhR[4], blR[4];
                LDSM4(bhR[0], bhR[1], bhR[2], bhR[3], bH + jo + bLane + ko);
                LDSM4(blR[0], blR[1], blR[2], blR[3], bL + jo + bLane + ko);
#pragma unroll
                for (int jj = 0; jj < 2; jj++) {
                    const int j = 2*jp + jj;
                    const uint32_t bh0 = bhR[jj], bh1 = bhR[jj+2];
                    const uint32_t bl0 = blR[jj], bl1 = blR[jj+2];
#pragma unroll
                    for (int mi = 0; mi < 2; mi++) {
                        mma16816(dacc[mi][j], ahf[mi][0], ahf[mi][1], ahf[mi][2], ahf[mi][3], bh0, bh1);
                        mma16816(dacc[mi][j], ahf[mi][0], ahf[mi][1], ahf[mi][2], ahf[mi][3], bl0, bl1);
                        mma16816(dacc[mi][j], alf[mi][0], alf[mi][1], alf[mi][2], alf[mi][3], bh0, bh1);
                    }
                }
            }
        }
    }

    // epilogue
    __nv_bfloat16 *oh = nullptr, *ol = nullptr;
    if (phase == 0) {
        oh = (z == 0) ? g_qh : (z == 1) ? g_kh : g_vh;
        ol = (z == 0) ? g_ql : (z == 1) ? g_kl : g_vl;
    }
#pragma unroll
    for (int mi = 0; mi < 2; mi++) {
        const int r0 = m0 + wr + mi*16 + g;
#pragma unroll
        for (int j = 0; j < 8; j++) {
            const int col = n0 + wc + 8*j + t2;
            float2 bs = *(const float2*)(bias + col);
            float v0 = dacc[mi][j][0] + bs.x, v1 = dacc[mi][j][1] + bs.y;
            float v2 = dacc[mi][j][2] + bs.x, v3 = dacc[mi][j][3] + bs.y;
            if (phase == 1) {
                *(float2*)(outp + (size_t)r0*512 + col) = make_float2(v0, v1);
                *(float2*)(outp + (size_t)(r0+8)*512 + col) = make_float2(v2, v3);
            } else {
                const int bidx = r0 >> 11, s = r0 & 2047;
                const int hh = col >> 6, d = col & 63;
                size_t o0 = ((size_t)(bidx*HH + hh)*SS + s)*64 + d;
                size_t o8 = o0 + 8*64;
                uint32_t h0 = packbf(v0, v1);
                *(uint32_t*)(oh + o0) = h0;
                *(uint32_t*)(ol + o0) = packres(v0, v1, h0);
                uint32_t h8 = packbf(v2, v3);
                *(uint32_t*)(oh + o8) = h8;
                *(uint32_t*)(ol + o8) = packres(v2, v3, h8);
            }
        }
    }
}

// ============================================================================
// Flash attention: ldmatrix(+trans) + cp.async 2-stage, ONE barrier per k-tile.
// Block=(h, 128 q-rows, b), 8 warps, warp owns 16 q-rows.
// ============================================================================
#define A_STRIDE 72
#define A_ARR    9216
#define A_STAGE  36864
#define A_SMEM   (2*A_STAGE)

__global__ __launch_bounds__(256, 2) void attn_kernel()
{
    extern __shared__ char smc[];
    const uint32_t sb = smem_u32(smc);

    const int tid = threadIdx.x;
    const int w = tid >> 5, lane = tid & 31;
    const int g = lane >> 2, t2 = (lane & 3) * 2;
    const int h = blockIdx.x, q0 = blockIdx.y * 128, b = blockIdx.z;
    const int mr = w * 16;
    const size_t bh = (size_t)(b*HH + h) * SS;

    // staging: 2 chunks per array per thread
    const int r0c = (tid*2) >> 3, c0c = ((tid*2) & 7) * 8;
    const int r1c = (tid*2+1) >> 3, c1c = ((tid*2+1) & 7) * 8;
    const uint32_t d0off = (uint32_t)(r0c*A_STRIDE + c0c) * 2;
    const uint32_t d1off = (uint32_t)(r1c*A_STRIDE + c1c) * 2;

    const uint32_t kLane = ((uint32_t)(lane & 7)*A_STRIDE + (lane >> 3)*8) * 2;
    const uint32_t vLane = (uint32_t)lane * A_STRIDE * 2;

    // ---- Q fragments, register-resident ----
    uint32_t qhf[4][4], qlf[4][4];
    {
        const __nv_bfloat16* qh = g_qh + (bh + q0 + mr) * DD;
        const __nv_bfloat16* ql = g_ql + (bh + q0 + mr) * DD;
#pragma unroll
        for (int kk = 0; kk < 4; kk++) {
            const int kb = kk*16 + t2;
            qhf[kk][0] = *(const uint32_t*)(qh + g*64 + kb);
            qhf[kk][1] = *(const uint32_t*)(qh + (g+8)*64 + kb);
            qhf[kk][2] = *(const uint32_t*)(qh + g*64 + kb + 8);
            qhf[kk][3] = *(const uint32_t*)(qh + (g+8)*64 + kb + 8);
            qlf[kk][0] = *(const uint32_t*)(ql + g*64 + kb);
            qlf[kk][1] = *(const uint32_t*)(ql + (g+8)*64 + kb);
            qlf[kk][2] = *(const uint32_t*)(ql + g*64 + kb + 8);
            qlf[kk][3] = *(const uint32_t*)(ql + (g+8)*64 + kb + 8);
        }
    }

    float oacc[8][4];
#pragma unroll
    for (int j = 0; j < 8; j++)
#pragma unroll
        for (int c = 0; c < 4; c++) oacc[j][c] = 0.f;
    float m0 = __int_as_float(0xff800000), m1 = m0;
    float l0 = 0.f, l1 = 0.f;

    auto issue = [&](int kt) {
        const uint32_t st = sb + (kt & 1) * A_STAGE;
        const size_t s0 = (bh + kt*64 + r0c) * 64 + c0c;
        const size_t s1 = (bh + kt*64 + r1c) * 64 + c1c;
        CP16(st + 0*A_ARR + d0off, g_kh + s0);  CP16(st + 0*A_ARR + d1off, g_kh + s1);
        CP16(st + 1*A_ARR + d0off, g_kl + s0);  CP16(st + 1*A_ARR + d1off, g_kl + s1);
        CP16(st + 2*A_ARR + d0off, g_vh + s0);  CP16(st + 2*A_ARR + d1off, g_vh + s1);
        CP16(st + 3*A_ARR + d0off, g_vl + s0);  CP16(st + 3*A_ARR + d1off, g_vl + s1);
    };

    issue(0); CPCOMMIT();

    for (int kt = 0; kt < 32; kt++) {
        CPWAIT(0);
        __syncthreads();            // stage kt published; stage kt^1 free
        if (kt < 31) { issue(kt+1); CPCOMMIT(); }

        // ---- mask words early (LDG in flight under the MMA burst) ----
        const size_t mrow = ((size_t)b*64 + kt*2)*SS + q0;
        const uint32_t mwa0 = g_mbits[mrow + mr + g];
        const uint32_t mwa1 = g_mbits[mrow + SS + mr + g];
        const uint32_t mwb0 = g_mbits[mrow + mr + g + 8];
        const uint32_t mwb1 = g_mbits[mrow + SS + mr + g + 8];

        const uint32_t st = sb + (kt & 1) * A_STAGE;
        const uint32_t kH = st, kL = st + A_ARR, vH = st + 2*A_ARR, vL = st + 3*A_ARR;

        // ---- scores: S = Q K^T (3-pass) ----
        float sacc[8][4];
#pragma unroll
        for (int j = 0; j < 8; j++)
#pragma unroll
            for (int c = 0; c < 4; c++) sacc[j][c] = 0.f;

#pragma unroll
        for (int j = 0; j < 8; j++) {
            const uint32_t jo = (uint32_t)(8*j*A_STRIDE) * 2;
            uint32_t bhR[8], blR[8];
            LDSM4(bhR[0], bhR[1], bhR[2], bhR[3], kH + jo + kLane);
            LDSM4(bhR[4], bhR[5], bhR[6], bhR[7], kH + jo + kLane + 64);
            LDSM4(blR[0], blR[1], blR[2], blR[3], kL + jo + kLane);
            LDSM4(blR[4], blR[5], blR[6], blR[7], kL + jo + kLane + 64);
#pragma unroll
            for (int kk = 0; kk < 4; kk++) {
                mma16816(sacc[j], qhf[kk][0], qhf[kk][1], qhf[kk][2], qhf[kk][3], bhR[2*kk], bhR[2*kk+1]);
                mma16816(sacc[j], qhf[kk][0], qhf[kk][1], qhf[kk][2], qhf[kk][3], blR[2*kk], blR[2*kk+1]);
                mma16816(sacc[j], qlf[kk][0], qlf[kk][1], qlf[kk][2], qlf[kk][3], bhR[2*kk], bhR[2*kk+1]);
            }
        }

        // ---- mask + scale ----
#pragma unroll
        for (int j = 0; j < 8; j++) {
            const int sh = (j & 3)*8 + t2;
            const uint32_t wa = (j < 4) ? mwa0 : mwa1;
            const uint32_t wb = (j < 4) ? mwb0 : mwb1;
            sacc[j][0] = (((wa >> sh) & 1)     ? sacc[j][0] : -1e9f) * 0.125f;
            sacc[j][1] = (((wa >> (sh+1)) & 1) ? sacc[j][1] : -1e9f) * 0.125f;
            sacc[j][2] = (((wb >> sh) & 1)     ? sacc[j][2] : -1e9f) * 0.125f;
            sacc[j][3] = (((wb >> (sh+1)) & 1) ? sacc[j][3] : -1e9f) * 0.125f;
        }

        // ---- online softmax ----
        float mx0 = sacc[0][0], mx1 = sacc[0][2];
#pragma unroll
        for (int j = 0; j < 8; j++) {
            mx0 = fmaxf(mx0, fmaxf(sacc[j][0], sacc[j][1]));
            mx1 = fmaxf(mx1, fmaxf(sacc[j][2], sacc[j][3]));
        }
#pragma unroll
        for (int o = 1; o <= 2; o <<= 1) {
            mx0 = fmaxf(mx0, __shfl_xor_sync(0xffffffffu, mx0, o));
            mx1 = fmaxf(mx1, __shfl_xor_sync(0xffffffffu, mx1, o));
        }
        const float nm0 = fmaxf(m0, mx0), nm1 = fmaxf(m1, mx1);
        const float cr0 = __expf(m0 - nm0), cr1 = __expf(m1 - nm1);
        m0 = nm0; m1 = nm1;

        float rs0 = 0.f, rs1 = 0.f;
#pragma unroll
        for (int j = 0; j < 8; j++) {
            sacc[j][0] = __expf(sacc[j][0] - nm0);
            sacc[j][1] = __expf(sacc[j][1] - nm0);
            sacc[j][2] = __expf(sacc[j][2] - nm1);
            sacc[j][3] = __expf(sacc[j][3] - nm1);
            rs0 += sacc[j][0] + sacc[j][1];
            rs1 += sacc[j][2] + sacc[j][3];
        }
#pragma unroll
        for (int o = 1; o <= 2; o <<= 1) {
            rs0 += __shfl_xor_sync(0xffffffffu, rs0, o);
            rs1 += __shfl_xor_sync(0xffffffffu, rs1, o);
        }
        l0 = l0 * cr0 + rs0;
        l1 = l1 * cr1 + rs1;
#pragma unroll
        for (int j = 0; j < 8; j++) {
            oacc[j][0] *= cr0; oacc[j][1] *= cr0;
            oacc[j][2] *= cr1; oacc[j][3] *= cr1;
        }

        // ---- pack P fragments (hi + residual lo) ----
        uint32_t pah[4][4], pal[4][4];
#pragma unroll
        for (int kk = 0; kk < 4; kk++) {
            const int j0 = 2*kk, j1 = 2*kk + 1;
            pah[kk][0] = packbf(sacc[j0][0], sacc[j0][1]);
            pah[kk][1] = packbf(sacc[j0][2], sacc[j0][3]);
            pah[kk][2] = packbf(sacc[j1][0], sacc[j1][1]);
            pah[kk][3] = packbf(sacc[j1][2], sacc[j1][3]);
            pal[kk][0] = packres(sacc[j0][0], sacc[j0][1], pah[kk][0]);
            pal[kk][1] = packres(sacc[j0][2], sacc[j0][3], pah[kk][1]);
            pal[kk][2] = packres(sacc[j1][0], sacc[j1][1], pah[kk][2]);
            pal[kk][3] = packres(sacc[j1][2], sacc[j1][3], pah[kk][3]);
        }

        // ---- PV (3-pass, V via ldmatrix.trans) ----
#pragma unroll
        for (int j2 = 0; j2 < 8; j2++) {
            const uint32_t jo = (uint32_t)(8*j2) * 2;
            uint32_t vhR[8], vlR[8];
            LDSM4T(vhR[0], vhR[1], vhR[2], vhR[3], vH + vLane + jo);
            LDSM4T(vhR[4], vhR[5], vhR[6], vhR[7], vH + vLane + jo + 32*A_STRIDE*2);
            LDSM4T(vlR[0], vlR[1], vlR[2], vlR[3], vL + vLane + jo);
            LDSM4T(vlR[4], vlR[5], vlR[6], vlR[7], vL + vLane + jo + 32*A_STRIDE*2);
#pragma unroll
            for (int kk = 0; kk < 4; kk++) {
                mma16816(oacc[j2], pah[kk][0], pah[kk][1], pah[kk][2], pah[kk][3], vhR[2*kk], vhR[2*kk+1]);
                mma16816(oacc[j2], pah[kk][0], pah[kk][1], pah[kk][2], pah[kk][3], vlR[2*kk], vlR[2*kk+1]);
                mma16816(oacc[j2], pal[kk][0], pal[kk][1], pal[kk][2], pal[kk][3], vhR[2*kk], vhR[2*kk+1]);
            }
        }
    }

    // ---- epilogue ----
    const float inv0 = 1.f / l0, inv1 = 1.f / l1;
    const size_t row0 = (size_t)b*SS + q0 + mr + g;
#pragma unroll
    for (int j2 = 0; j2 < 8; j2++) {
        const int d = 8*j2 + t2;
        float v0 = oacc[j2][0] * inv0, v1 = oacc[j2][1] * inv0;
        float v2 = oacc[j2][2] * inv1, v3 = oacc[j2][3] * inv1;
        uint32_t h0 = packbf(v0, v1);
        *(uint32_t*)(g_oh + row0*512 + h*64 + d) = h0;
        *(uint32_t*)(g_ol + row0*512 + h*64 + d) = packres(v0, v1, h0);
        uint32_t h8 = packbf(v2, v3);
        *(uint32_t*)(g_oh + (row0+8)*512 + h*64 + d) = h8;
        *(uint32_t*)(g_ol + (row0+8)*512 + h*64 + d) = packres(v2, v3, h8);
    }
}

// ============================================================================
extern "C" void kernel_launch(void* const* d_in, const int* in_sizes, int n_in,
                              void* d_out, int out_size)
{
    const float* iq   = (const float*)d_in[0];
    const float* ik   = (const float*)d_in[1];
    const float* iv   = (const float*)d_in[2];
    const int*   mask = (const int*)  d_in[3];
    const float* wq   = (const float*)d_in[4];
    const float* bq   = (const float*)d_in[5];
    const float* wk   = (const float*)d_in[6];
    const float* bk   = (const float*)d_in[7];
    const float* wv   = (const float*)d_in[8];
    const float* bv   = (const float*)d_in[9];
    const float* wo   = (const float*)d_in[10];
    const float* bo   = (const float*)d_in[11];
    float* out = (float*)d_out;

    cudaFuncSetAttribute(gemm_mma_kernel, cudaFuncAttributeMaxDynamicSharedMemorySize, G_SMEM);
    cudaFuncSetAttribute(attn_kernel, cudaFuncAttributeMaxDynamicSharedMemorySize, A_SMEM);

    split_act_kernel<<<dim3(MKELEM/4/256, 1, 3), 256>>>(iq, ik, iv);
    wsplit_kernel<<<dim3(16, 16, 4), dim3(32, 8)>>>(wq, wk, wv, wo);
    maskpack_kernel<<<BB*SS*64/8, 256>>>(mask);
    gemm_mma_kernel<<<dim3(4, 64, 3), 256, G_SMEM>>>(0, bq, bk, bv, nullptr);
    attn_kernel<<<dim3(HH, SS/128, BB), 256, A_SMEM>>>();
    gemm_mma_kernel<<<dim3(4, 64, 1), 256, G_SMEM>>>(1, bo, nullptr, nullptr, out);
}